// round 6
// baseline (speedup 1.0000x reference)
#include <cuda_runtime.h>
#include <math.h>

#define B_    64
#define T_    512
#define NHID_ 1024
#define NG_   4096
#define NTOK_ 2048
#define NINP_ 512
#define NB_   128        // persistent CTAs (one per 8 hidden units)

// ---------------- device scratch (static: no allocations) ----------------
__device__ float d_P[(size_t)NTOK_ * NG_];       // 32 MB per-token low-gate base
__device__ float d_hl[2][B_ * NHID_];            // ping-pong low hidden
__device__ float d_hh[2][B_ * NHID_];            // ping-pong high hidden
__device__ float d_hs[(size_t)T_ * B_ * NHID_];  // h_low per step, [t][b][k]
__device__ float d_biasHi[NG_];
__device__ unsigned g_cnt;                        // grid barrier state
__device__ unsigned g_gen;

// ---------------- helpers ----------------
__device__ __forceinline__ unsigned tf(float f) {
    unsigned u;
    asm("cvt.rna.tf32.f32 %0, %1;" : "=r"(u) : "f"(f));
    return u;
}

__device__ __forceinline__ void mma_tf32(float* d, const unsigned* a, const unsigned* b) {
    asm volatile(
        "mma.sync.aligned.m16n8k8.row.col.f32.tf32.tf32.f32 "
        "{%0,%1,%2,%3},{%4,%5,%6,%7},{%8,%9},{%0,%1,%2,%3};\n"
        : "+f"(d[0]), "+f"(d[1]), "+f"(d[2]), "+f"(d[3])
        : "r"(a[0]), "r"(a[1]), "r"(a[2]), "r"(a[3]), "r"(b[0]), "r"(b[1]));
}

__device__ __forceinline__ void sts4(unsigned* dst, float4 v) {
    dst[0] = tf(v.x); dst[1] = tf(v.y); dst[2] = tf(v.z); dst[3] = tf(v.w);
}

__device__ __forceinline__ float4 ldcg4(const float* p) {
    return __ldcg((const float4*)p);
}

__device__ __forceinline__ float sigm(float x) { return 1.0f / (1.0f + expf(-x)); }

// Grid-wide barrier: release-fence + arrive; leader of last CTA flips gen.
__device__ __forceinline__ void gridbar() {
    __threadfence();
    __syncthreads();
    if (threadIdx.x == 0) {
        unsigned gen = *(volatile unsigned*)&g_gen;
        unsigned prev = atomicAdd(&g_cnt, 1u);
        if (prev == NB_ - 1) {
            atomicExch(&g_cnt, 0u);
            __threadfence();
            atomicExch(&g_gen, gen + 1u);
        } else {
            while (*(volatile unsigned*)&g_gen == gen) __nanosleep(40);
        }
    }
    __syncthreads();
}

// ---------------- in-kernel gate GEMM for one phase ----------------
// sg[64 x 32] = A0[64 x 1024] @ W0_rows^T + A1[64 x 1024] @ W1_rows^T
// Columns are bundled (gate g, unit u): col = g*8+u, W row = g*NHID + u0 + u.
// A matrices are mutable cross-CTA state -> read via ld.global.cg.
__device__ __forceinline__ void gemm_phase(
    unsigned (&As)[64][36], unsigned (&Ws)[32][36], float (&sg)[64][32],
    const float* __restrict__ A0, const float* __restrict__ A1,
    const float* __restrict__ W0, int ldw0,
    const float* __restrict__ W1, int ldw1, int u0)
{
    const int tid = threadIdx.x, lane = tid & 31, wid = tid >> 5;
    const int r = tid >> 3;
    const int c4 = (tid & 7) * 4;
    const int jg = (r >> 3) * NHID_ + u0 + (r & 7);

    const float* a0r  = A0 + (size_t)r * NHID_;
    const float* a0r2 = A0 + (size_t)(r + 32) * NHID_;
    const float* a1r  = A1 + (size_t)r * NHID_;
    const float* a1r2 = A1 + (size_t)(r + 32) * NHID_;
    const float* w0r  = W0 + (size_t)jg * ldw0;
    const float* w1r  = W1 + (size_t)jg * ldw1;

    float4 pa = ldcg4(a0r + c4);
    float4 pb = ldcg4(a0r2 + c4);
    float4 pw = *(const float4*)(w0r + c4);

    const int mw = wid >> 1, nw = wid & 1;
    float acc[2][4] = {};

    for (int kc = 0; kc < 64; kc++) {
        sts4(&As[r][c4], pa);
        sts4(&As[r + 32][c4], pb);
        sts4(&Ws[r][c4], pw);
        __syncthreads();
        if (kc + 1 < 64) {
            int kn = kc + 1;
            if (kn < 32) {
                int ko = kn * 32 + c4;
                pa = ldcg4(a0r + ko);
                pb = ldcg4(a0r2 + ko);
                pw = *(const float4*)(w0r + ko);
            } else {
                int ko = (kn - 32) * 32 + c4;
                pa = ldcg4(a1r + ko);
                pb = ldcg4(a1r2 + ko);
                pw = *(const float4*)(w1r + ko);
            }
        }
#pragma unroll
        for (int kk = 0; kk < 4; kk++) {
            const int ak = kk * 8 + (lane & 3);
            const int ar = mw * 16 + (lane >> 2);
            unsigned a[4];
            a[0] = As[ar][ak];     a[1] = As[ar + 8][ak];
            a[2] = As[ar][ak + 4]; a[3] = As[ar + 8][ak + 4];
#pragma unroll
            for (int nt = 0; nt < 2; nt++) {
                const int br = nw * 16 + nt * 8 + (lane >> 2);
                unsigned bb[2];
                bb[0] = Ws[br][ak]; bb[1] = Ws[br][ak + 4];
                mma_tf32(acc[nt], a, bb);
            }
        }
        __syncthreads();
    }

    {
        int er = mw * 16 + (lane >> 2);
        int ec = nw * 16 + (lane & 3) * 2;
#pragma unroll
        for (int nt = 0; nt < 2; nt++) {
            int c = ec + nt * 8;
            sg[er][c]         = acc[nt][0];
            sg[er][c + 1]     = acc[nt][1];
            sg[er + 8][c]     = acc[nt][2];
            sg[er + 8][c + 1] = acc[nt][3];
        }
    }
    __syncthreads();
}

// ---------------- persistent recurrence kernel ----------------
__global__ void __launch_bounds__(256, 1) hrnn_persist(
    const int* __restrict__ tokens, const int* __restrict__ measure,
    const float* __restrict__ Wil, const float* __restrict__ Whl,
    const float* __restrict__ Wih, const float* __restrict__ Whh,
    const float* __restrict__ c0l, const float* __restrict__ c0h,
    float* __restrict__ out, int out_size)
{
    __shared__ unsigned As[64][36];
    __shared__ unsigned Ws[32][36];
    __shared__ float    sg[64][32];

    const int tid = threadIdx.x;
    const int u0 = blockIdx.x * 8;

    float* hl0 = d_hl[0]; float* hl1 = d_hl[1];
    float* hh0 = d_hh[0]; float* hh1 = d_hh[1];

    // epilogue ownership: (b, u) pairs for it = 0,1
    const int bA = tid >> 3;           // 0..31
    const int uA = tid & 7;
    const int unit = u0 + uA;
    const int bArr[2] = { bA, bA + 32 };

    float cl[2], ch[2];
#pragma unroll
    for (int it = 0; it < 2; it++) {
        cl[it] = c0l[bArr[it] * NHID_ + unit];
        ch[it] = c0h[bArr[it] * NHID_ + unit];
    }
    const int mval = *measure;

    for (int t = 0; t < T_; t++) {
        float* hlA = (t & 1) ? hl1 : hl0;
        float* hlN = (t & 1) ? hl0 : hl1;
        float* hhA = (t & 1) ? hh1 : hh0;
        float* hhN = (t & 1) ? hh0 : hh1;

        // ---- low cell: inp = [emb(tok) | h_h] ; emb part folded into d_P ----
        gemm_phase(As, Ws, sg, hhA, hlA,
                   Wil + NINP_, NINP_ + NHID_, Whl, NHID_, u0);
#pragma unroll
        for (int it = 0; it < 2; it++) {
            int b = bArr[it];
            int tok = tokens[b * T_ + t];
            const float* bp = d_P + (size_t)tok * NG_ + unit;
            float gi = sg[b][uA]      + bp[0];
            float gf = sg[b][8 + uA]  + bp[NHID_];
            float gg = sg[b][16 + uA] + bp[2 * NHID_];
            float go = sg[b][24 + uA] + bp[3 * NHID_];
            float cn = sigm(gf) * cl[it] + sigm(gi) * tanhf(gg);
            float hn = sigm(go) * tanhf(cn);
            cl[it] = cn;
            hlN[b * NHID_ + unit] = hn;
            d_hs[((size_t)t * B_ + b) * NHID_ + unit] = hn;
        }
        gridbar();

        // ---- high cell: masked update ----
        gemm_phase(As, Ws, sg, hlN, hhA, Wih, NHID_, Whh, NHID_, u0);
#pragma unroll
        for (int it = 0; it < 2; it++) {
            int b = bArr[it];
            const float* bp = d_biasHi + unit;
            float gi = sg[b][uA]      + bp[0];
            float gf = sg[b][8 + uA]  + bp[NHID_];
            float gg = sg[b][16 + uA] + bp[2 * NHID_];
            float go = sg[b][24 + uA] + bp[3 * NHID_];
            float cn = sigm(gf) * ch[it] + sigm(gi) * tanhf(gg);
            float hn = sigm(go) * tanhf(cn);
            bool m = (tokens[b * T_ + t] == mval);
            ch[it] = m ? cn : ch[it];
            hhN[b * NHID_ + unit] =
                m ? hn : __ldcg(&hhA[b * NHID_ + unit]);
        }
        gridbar();
    }

    // final states (t=511 wrote ping 0); c is still in registers.
    size_t q = (size_t)B_ * T_ * NTOK_;
    size_t S = (size_t)B_ * NHID_;
    if ((size_t)out_size >= q + 4 * S) {
#pragma unroll
        for (int it = 0; it < 2; it++) {
            size_t o = (size_t)bArr[it] * NHID_ + unit;
            out[q + o]         = __ldcg(&hl0[o]);
            out[q + S + o]     = cl[it];
            out[q + 2 * S + o] = __ldcg(&hh0[o]);
            out[q + 3 * S + o] = ch[it];
        }
    }
}

// ---------------- generic tf32 GEMM: C[MxN] = A[MxK] @ Bw[N,K]^T + bias ----
// REMAP=1: A rows come from d_hs [t][b][k], output row r = b*T + t.
template <int REMAP>
__global__ void __launch_bounds__(256) gemm_k(
    const float* __restrict__ A, int lda,
    const float* __restrict__ Bw, int ldb,
    const float* __restrict__ bias1, const float* __restrict__ bias2,
    float* __restrict__ C, int ldc, int K)
{
    __shared__ unsigned As[64][36];
    __shared__ unsigned Bs[64][36];

    const int tid = threadIdx.x, lane = tid & 31, wid = tid >> 5;
    const int m0 = blockIdx.y * 64, n0 = blockIdx.x * 64;

    const float* Ab;
    long as;
    if (REMAP) {
        Ab = A + ((size_t)(m0 % T_) * B_ + (m0 / T_)) * NHID_;
        as = (long)B_ * NHID_;
    } else {
        Ab = A + (size_t)m0 * lda;
        as = lda;
    }

    const int r = tid >> 3, c4 = (tid & 7) * 4;
    float4 pa0 = *(const float4*)(Ab + (long)r * as + c4);
    float4 pa1 = *(const float4*)(Ab + (long)(r + 32) * as + c4);
    float4 pb0 = *(const float4*)(Bw + (size_t)(n0 + r) * ldb + c4);
    float4 pb1 = *(const float4*)(Bw + (size_t)(n0 + r + 32) * ldb + c4);

    const int mw = wid >> 1, nw = wid & 1;
    float acc[4][4] = {};

    const int nch = K / 32;
    for (int kc = 0; kc < nch; kc++) {
        sts4(&As[r][c4], pa0);
        sts4(&As[r + 32][c4], pa1);
        sts4(&Bs[r][c4], pb0);
        sts4(&Bs[r + 32][c4], pb1);
        __syncthreads();
        if (kc + 1 < nch) {
            int ko = (kc + 1) * 32 + c4;
            pa0 = *(const float4*)(Ab + (long)r * as + ko);
            pa1 = *(const float4*)(Ab + (long)(r + 32) * as + ko);
            pb0 = *(const float4*)(Bw + (size_t)(n0 + r) * ldb + ko);
            pb1 = *(const float4*)(Bw + (size_t)(n0 + r + 32) * ldb + ko);
        }
#pragma unroll
        for (int kk = 0; kk < 4; kk++) {
            const int ak = kk * 8 + (lane & 3);
            const int ar = mw * 16 + (lane >> 2);
            unsigned a[4];
            a[0] = As[ar][ak];     a[1] = As[ar + 8][ak];
            a[2] = As[ar][ak + 4]; a[3] = As[ar + 8][ak + 4];
#pragma unroll
            for (int nt = 0; nt < 4; nt++) {
                const int br = nw * 32 + nt * 8 + (lane >> 2);
                unsigned bb[2];
                bb[0] = Bs[br][ak]; bb[1] = Bs[br][ak + 4];
                mma_tf32(acc[nt], a, bb);
            }
        }
        __syncthreads();
    }

    const int er = m0 + mw * 16 + (lane >> 2);
    const int ec0 = n0 + nw * 32 + (lane & 3) * 2;
#pragma unroll
    for (int nt = 0; nt < 4; nt++) {
        int c = ec0 + nt * 8;
        float bv0 = bias1[c]     + (bias2 ? bias2[c]     : 0.0f);
        float bv1 = bias1[c + 1] + (bias2 ? bias2[c + 1] : 0.0f);
        *(float2*)&C[(size_t)er * ldc + c] =
            make_float2(acc[nt][0] + bv0, acc[nt][1] + bv1);
        *(float2*)&C[(size_t)(er + 8) * ldc + c] =
            make_float2(acc[nt][2] + bv0, acc[nt][3] + bv1);
    }
}

// ---------------- init ----------------
__global__ void init_k(const float* h0l, const float* h0h,
                       const float* bih, const float* bhh)
{
    int i = blockIdx.x * blockDim.x + threadIdx.x;
    if (i < B_ * NHID_) {
        d_hl[0][i] = h0l[i];
        d_hh[0][i] = h0h[i];
    }
    if (i < NG_) d_biasHi[i] = bih[i] + bhh[i];
}

// ---------------- launch ----------------
extern "C" void kernel_launch(void* const* d_in, const int* in_sizes, int n_in,
                              void* d_out, int out_size)
{
    const int*   tokens  = (const int*)d_in[0];
    const int*   measure = (const int*)d_in[1];
    const float* emb     = (const float*)d_in[2];
    const float* Wil     = (const float*)d_in[3];   // [4096][1536]
    const float* Whl     = (const float*)d_in[4];   // [4096][1024]
    const float* bil     = (const float*)d_in[5];
    const float* bhl     = (const float*)d_in[6];
    const float* Wih     = (const float*)d_in[7];   // [4096][1024]
    const float* Whh     = (const float*)d_in[8];   // [4096][1024]
    const float* bih     = (const float*)d_in[9];
    const float* bhh     = (const float*)d_in[10];
    const float* Wd      = (const float*)d_in[11];  // [2048][1024]
    const float* bd      = (const float*)d_in[12];
    const float* h0l     = (const float*)d_in[13];
    const float* c0l     = (const float*)d_in[14];
    const float* h0h     = (const float*)d_in[15];
    const float* c0h     = (const float*)d_in[16];
    float* out = (float*)d_out;

    void* p;
    cudaGetSymbolAddress(&p, d_P);  float* Pp  = (float*)p;
    cudaGetSymbolAddress(&p, d_hs); float* hsP = (float*)p;

    init_k<<<256, 256>>>(h0l, h0h, bih, bhh);

    // P[v][j] = emb[v,:512] @ W_ih_low[j,:512]^T + b_ih_low[j] + b_hh_low[j]
    gemm_k<0><<<dim3(NG_ / 64, NTOK_ / 64), 256>>>(
        emb, NINP_, Wil, NINP_ + NHID_, bil, bhl, Pp, NG_, NINP_);

    // entire 512-step recurrence in one persistent kernel
    hrnn_persist<<<NB_, 256>>>(tokens, measure, Wil, Whl, Wih, Whh,
                               c0l, c0h, out, out_size);

    // decode: out[b*T+t][n] = hs[t][b][:] @ W_dec[n][:]^T + b_dec[n]
    gemm_k<1><<<dim3(NTOK_ / 64, (B_ * T_) / 64), 256>>>(
        hsP, 0, Wd, NHID_, bd, (const float*)0, out, NTOK_, NHID_);
}

// round 7
// speedup vs baseline: 1.1889x; 1.1889x over previous
#include <cuda_runtime.h>
#include <math.h>

#define B_    64
#define T_    512
#define NHID_ 1024
#define NG_   4096
#define NTOK_ 2048
#define NINP_ 512
#define NB_   128            // persistent CTAs (one per 8 hidden units)
#define WPC_  65536ULL       // packed-W words per (phase, ub): 64 chunks * 1024

// ---------------- device scratch (static: no allocations) ----------------
__device__ float d_P[(size_t)NTOK_ * NG_];       // 32 MB per-token low-gate base
__device__ float d_hl[2][B_ * NHID_];
__device__ float d_hh[2][B_ * NHID_];
__device__ float d_hs[(size_t)T_ * B_ * NHID_];  // h_low per step, [t][b][k]
__device__ float d_biasHi[NG_];
__device__ float d_Wp[2ULL * NB_ * WPC_];        // 64 MB frag-packed tf32 weights
__device__ unsigned g_cnt;
__device__ unsigned g_gen;

// ---------------- helpers ----------------
__device__ __forceinline__ unsigned tf(float f) {
    unsigned u;
    asm("cvt.rna.tf32.f32 %0, %1;" : "=r"(u) : "f"(f));
    return u;
}

__device__ __forceinline__ void mma_tf32(float* d, const unsigned* a,
                                         unsigned b0, unsigned b1) {
    asm volatile(
        "mma.sync.aligned.m16n8k8.row.col.f32.tf32.tf32.f32 "
        "{%0,%1,%2,%3},{%4,%5,%6,%7},{%8,%9},{%0,%1,%2,%3};\n"
        : "+f"(d[0]), "+f"(d[1]), "+f"(d[2]), "+f"(d[3])
        : "r"(a[0]), "r"(a[1]), "r"(a[2]), "r"(a[3]), "r"(b0), "r"(b1));
}

__device__ __forceinline__ float4 ldcg4(const float* p) {
    return __ldcg((const float4*)p);
}

__device__ __forceinline__ uint4 tf4(float4 v) {
    return make_uint4(tf(v.x), tf(v.y), tf(v.z), tf(v.w));
}

__device__ __forceinline__ float sigm(float x) { return 1.0f / (1.0f + expf(-x)); }

// Grid-wide barrier
__device__ __forceinline__ void gridbar() {
    __threadfence();
    __syncthreads();
    if (threadIdx.x == 0) {
        unsigned gen = *(volatile unsigned*)&g_gen;
        unsigned prev = atomicAdd(&g_cnt, 1u);
        if (prev == NB_ - 1) {
            atomicExch(&g_cnt, 0u);
            __threadfence();
            atomicExch(&g_gen, gen + 1u);
        } else {
            while (*(volatile unsigned*)&g_gen == gen) __nanosleep(32);
        }
    }
    __syncthreads();
}

// ---------------- weight prepack: frag-ready tf32 layout ----------------
// out[(ub,kc)] block of 1024 words = 512 uint2, entry index
//   nw*256 + kk*64 + nt*32 + lane  (== threadIdx.x), holding
//   {W[n][k], W[n][k+4]} with n = nw*16+nt*8+(lane>>2) (gate-col),
//   k = kc*32 + kk*8 + (lane&3). Gate-col n maps to row (n>>3)*NHID + ub*8 + (n&7).
__global__ void __launch_bounds__(512) prepack_k(
    const float* __restrict__ W0, int ldw0, int col0,
    const float* __restrict__ W1, int ldw1,
    float* __restrict__ outp)
{
    const int kc = blockIdx.x, ub = blockIdx.y;
    const int t = threadIdx.x;
    const int lane = t & 31, nt = (t >> 5) & 1, kk = (t >> 6) & 3, nw = (t >> 8) & 1;
    const int n = nw * 16 + nt * 8 + (lane >> 2);
    const int row = (n >> 3) * NHID_ + ub * 8 + (n & 7);
    const int k = kc * 32 + kk * 8 + (lane & 3);
    float v0, v1;
    if (kc < 32) {
        v0 = W0[(size_t)row * ldw0 + col0 + k];
        v1 = W0[(size_t)row * ldw0 + col0 + k + 4];
    } else {
        v0 = W1[(size_t)row * ldw1 + (k - 1024)];
        v1 = W1[(size_t)row * ldw1 + (k - 1024) + 4];
    }
    uint2* o = (uint2*)(outp + (size_t)ub * WPC_ + (size_t)kc * 1024);
    o[t] = make_uint2(tf(v0), tf(v1));
}

// ---------------- pipelined chunk body (CUR = smem buffer parity) ----------
template <int CUR>
__device__ __forceinline__ void chunk_body(
    int kc,
    unsigned (&As)[2][64][36],
    uint2 (&w)[2][8],
    float4& pa, float4& pb,
    float (&acc)[2][4],
    const float* a0r, const float* a0r2,
    const float* a1r, const float* a1r2,
    const uint2* wb,
    int lane, int mw, int r, int c4)
{
    if (kc < 63) {
        // W frags for chunk kc+1 -> alternate reg set
        const uint2* wc = wb + (size_t)(kc + 1) * 512;
#pragma unroll
        for (int q = 0; q < 8; q++)
            w[CUR ^ 1][q] = __ldg(wc + (q >> 1) * 64 + (q & 1) * 32);
        // stage A chunk kc+1 into alternate smem buffer (data prefetched earlier)
        *(uint4*)&As[CUR ^ 1][r][c4]      = tf4(pa);
        *(uint4*)&As[CUR ^ 1][r + 32][c4] = tf4(pb);
        if (kc < 62) {
            int kn = kc + 2;
            if (kn < 32) { pa = ldcg4(a0r + kn * 32); pb = ldcg4(a0r2 + kn * 32); }
            else { pa = ldcg4(a1r + (kn - 32) * 32); pb = ldcg4(a1r2 + (kn - 32) * 32); }
        }
    }
    // compute chunk kc
#pragma unroll
    for (int kk = 0; kk < 4; kk++) {
        const int ak = kk * 8 + (lane & 3);
        const int ar = mw * 16 + (lane >> 2);
        unsigned a[4];
        a[0] = As[CUR][ar][ak];     a[1] = As[CUR][ar + 8][ak];
        a[2] = As[CUR][ar][ak + 4]; a[3] = As[CUR][ar + 8][ak + 4];
#pragma unroll
        for (int nt = 0; nt < 2; nt++)
            mma_tf32(acc[nt], a, w[CUR][kk * 2 + nt].x, w[CUR][kk * 2 + nt].y);
    }
    __syncthreads();
}

// ---------------- gate GEMM for one phase ----------------
// sg[64 x 32] = A0[64x1024] @ W0^T + A1[64x1024] @ W1^T (W prepacked in Wp)
__device__ __forceinline__ void gemm_phase(
    unsigned (&As)[2][64][36], float (&sg)[64][32],
    const float* __restrict__ A0, const float* __restrict__ A1,
    const uint2* __restrict__ Wp)
{
    const int tid = threadIdx.x, lane = tid & 31, wid = tid >> 5;
    const int r = tid >> 3, c4 = (tid & 7) * 4;
    const int mw = wid >> 1, nw = wid & 1;

    const float* a0r  = A0 + (size_t)r * NHID_ + c4;
    const float* a0r2 = A0 + (size_t)(r + 32) * NHID_ + c4;
    const float* a1r  = A1 + (size_t)r * NHID_ + c4;
    const float* a1r2 = A1 + (size_t)(r + 32) * NHID_ + c4;
    const uint2* wb = Wp + nw * 256 + lane;

    // preamble: chunk 0 staged, chunk 1 in flight
    float4 pa = ldcg4(a0r), pb = ldcg4(a0r2);
    uint2 w[2][8];
#pragma unroll
    for (int q = 0; q < 8; q++)
        w[0][q] = __ldg(wb + (q >> 1) * 64 + (q & 1) * 32);
    *(uint4*)&As[0][r][c4]      = tf4(pa);
    *(uint4*)&As[0][r + 32][c4] = tf4(pb);
    pa = ldcg4(a0r + 32); pb = ldcg4(a0r2 + 32);
    __syncthreads();

    float acc[2][4] = {};
    for (int kb = 0; kb < 32; kb++) {
        chunk_body<0>(kb * 2,     As, w, pa, pb, acc, a0r, a0r2, a1r, a1r2, wb, lane, mw, r, c4);
        chunk_body<1>(kb * 2 + 1, As, w, pa, pb, acc, a0r, a0r2, a1r, a1r2, wb, lane, mw, r, c4);
    }

    // dump accumulators: sg[batch][gate*8+u]
    {
        int er = mw * 16 + (lane >> 2);
        int ec = nw * 16 + (lane & 3) * 2;
#pragma unroll
        for (int nt = 0; nt < 2; nt++) {
            int c = ec + nt * 8;
            sg[er][c]         = acc[nt][0];
            sg[er][c + 1]     = acc[nt][1];
            sg[er + 8][c]     = acc[nt][2];
            sg[er + 8][c + 1] = acc[nt][3];
        }
    }
    __syncthreads();
}

// ---------------- persistent recurrence kernel ----------------
__global__ void __launch_bounds__(256, 1) hrnn_persist(
    const int* __restrict__ tokens, const int* __restrict__ measure,
    const float* __restrict__ c0l, const float* __restrict__ c0h,
    float* __restrict__ out, int out_size)
{
    __shared__ unsigned As[2][64][36];
    __shared__ float    sg[64][32];

    const int tid = threadIdx.x;
    const int u0 = blockIdx.x * 8;
    const uint2* WpL = (const uint2*)(d_Wp + (size_t)blockIdx.x * WPC_);
    const uint2* WpH = (const uint2*)(d_Wp + (size_t)(NB_ + blockIdx.x) * WPC_);

    float* hl0 = d_hl[0]; float* hl1 = d_hl[1];
    float* hh0 = d_hh[0]; float* hh1 = d_hh[1];

    const int bA = tid >> 3;
    const int uA = tid & 7;
    const int unit = u0 + uA;
    const int bArr[2] = { bA, bA + 32 };

    float cl[2], ch[2], bv[2][4];
#pragma unroll
    for (int it = 0; it < 2; it++) {
        cl[it] = c0l[bArr[it] * NHID_ + unit];
        ch[it] = c0h[bArr[it] * NHID_ + unit];
    }
#pragma unroll
    for (int g = 0; g < 4; g++) {
        bv[0][g] = __ldg(&d_biasHi[g * NHID_ + unit]);
        bv[1][g] = bv[0][g];
    }
    const int mval = *measure;

    for (int t = 0; t < T_; t++) {
        float* hlA = (t & 1) ? hl1 : hl0;
        float* hlN = (t & 1) ? hl0 : hl1;
        float* hhA = (t & 1) ? hh1 : hh0;
        float* hhN = (t & 1) ? hh0 : hh1;

        // prefetch epilogue operands for the low phase
        int tok[2];
        float pv[2][4];
#pragma unroll
        for (int it = 0; it < 2; it++) {
            tok[it] = __ldg(&tokens[bArr[it] * T_ + t]);
            const float* bp = d_P + (size_t)tok[it] * NG_ + unit;
#pragma unroll
            for (int g = 0; g < 4; g++) pv[it][g] = __ldg(bp + g * NHID_);
        }

        // ---- low cell: inp = [emb(tok) | h_h]; emb folded into d_P ----
        gemm_phase(As, sg, hhA, hlA, WpL);
#pragma unroll
        for (int it = 0; it < 2; it++) {
            int b = bArr[it];
            float gi = sg[b][uA]      + pv[it][0];
            float gf = sg[b][8 + uA]  + pv[it][1];
            float gg = sg[b][16 + uA] + pv[it][2];
            float go = sg[b][24 + uA] + pv[it][3];
            float cn = sigm(gf) * cl[it] + sigm(gi) * tanhf(gg);
            float hn = sigm(go) * tanhf(cn);
            cl[it] = cn;
            hlN[b * NHID_ + unit] = hn;
            d_hs[((size_t)t * B_ + b) * NHID_ + unit] = hn;
        }
        gridbar();

        // prefetch for high epilogue: previous high h (kept when unmasked)
        float hp[2];
#pragma unroll
        for (int it = 0; it < 2; it++)
            hp[it] = __ldcg(&hhA[bArr[it] * NHID_ + unit]);

        // ---- high cell: masked update ----
        gemm_phase(As, sg, hlN, hhA, WpH);
#pragma unroll
        for (int it = 0; it < 2; it++) {
            int b = bArr[it];
            float gi = sg[b][uA]      + bv[it][0];
            float gf = sg[b][8 + uA]  + bv[it][1];
            float gg = sg[b][16 + uA] + bv[it][2];
            float go = sg[b][24 + uA] + bv[it][3];
            float cn = sigm(gf) * ch[it] + sigm(gi) * tanhf(gg);
            float hn = sigm(go) * tanhf(cn);
            bool m = (tok[it] == mval);
            ch[it] = m ? cn : ch[it];
            hhN[b * NHID_ + unit] = m ? hn : hp[it];
        }
        gridbar();
    }

    // final states (t=511 wrote ping 0); c still in registers
    size_t q = (size_t)B_ * T_ * NTOK_;
    size_t S = (size_t)B_ * NHID_;
    if ((size_t)out_size >= q + 4 * S) {
#pragma unroll
        for (int it = 0; it < 2; it++) {
            size_t o = (size_t)bArr[it] * NHID_ + unit;
            out[q + o]         = __ldcg(&hl0[o]);
            out[q + S + o]     = cl[it];
            out[q + 2 * S + o] = __ldcg(&hh0[o]);
            out[q + 3 * S + o] = ch[it];
        }
    }
}

// ---------------- generic tf32 GEMM: C[MxN] = A[MxK] @ Bw[N,K]^T + bias ----
template <int REMAP>
__global__ void __launch_bounds__(256) gemm_k(
    const float* __restrict__ A, int lda,
    const float* __restrict__ Bw, int ldb,
    const float* __restrict__ bias1, const float* __restrict__ bias2,
    float* __restrict__ C, int ldc, int K)
{
    __shared__ unsigned As[64][36];
    __shared__ unsigned Bs[64][36];

    const int tid = threadIdx.x, lane = tid & 31, wid = tid >> 5;
    const int m0 = blockIdx.y * 64, n0 = blockIdx.x * 64;

    const float* Ab;
    long as;
    if (REMAP) {
        Ab = A + ((size_t)(m0 % T_) * B_ + (m0 / T_)) * NHID_;
        as = (long)B_ * NHID_;
    } else {
        Ab = A + (size_t)m0 * lda;
        as = lda;
    }

    const int r = tid >> 3, c4 = (tid & 7) * 4;
    float4 pa0 = *(const float4*)(Ab + (long)r * as + c4);
    float4 pa1 = *(const float4*)(Ab + (long)(r + 32) * as + c4);
    float4 pb0 = *(const float4*)(Bw + (size_t)(n0 + r) * ldb + c4);
    float4 pb1 = *(const float4*)(Bw + (size_t)(n0 + r + 32) * ldb + c4);

    const int mw = wid >> 1, nw = wid & 1;
    float acc[4][4] = {};

    const int nch = K / 32;
    for (int kc = 0; kc < nch; kc++) {
        *(uint4*)&As[r][c4]      = tf4(pa0);
        *(uint4*)&As[r + 32][c4] = tf4(pa1);
        *(uint4*)&Bs[r][c4]      = tf4(pb0);
        *(uint4*)&Bs[r + 32][c4] = tf4(pb1);
        __syncthreads();
        if (kc + 1 < nch) {
            int ko = (kc + 1) * 32 + c4;
            pa0 = *(const float4*)(Ab + (long)r * as + ko);
            pa1 = *(const float4*)(Ab + (long)(r + 32) * as + ko);
            pb0 = *(const float4*)(Bw + (size_t)(n0 + r) * ldb + ko);
            pb1 = *(const float4*)(Bw + (size_t)(n0 + r + 32) * ldb + ko);
        }
#pragma unroll
        for (int kk = 0; kk < 4; kk++) {
            const int ak = kk * 8 + (lane & 3);
            const int ar = mw * 16 + (lane >> 2);
            unsigned a[4];
            a[0] = As[ar][ak];     a[1] = As[ar + 8][ak];
            a[2] = As[ar][ak + 4]; a[3] = As[ar + 8][ak + 4];
#pragma unroll
            for (int nt = 0; nt < 4; nt++) {
                const int br = nw * 32 + nt * 8 + (lane >> 2);
                mma_tf32(acc[nt], a, Bs[br][ak], Bs[br][ak + 4]);
            }
        }
        __syncthreads();
    }

    const int er = m0 + mw * 16 + (lane >> 2);
    const int ec0 = n0 + nw * 32 + (lane & 3) * 2;
#pragma unroll
    for (int nt = 0; nt < 4; nt++) {
        int c = ec0 + nt * 8;
        float bv0 = bias1[c]     + (bias2 ? bias2[c]     : 0.0f);
        float bv1 = bias1[c + 1] + (bias2 ? bias2[c + 1] : 0.0f);
        *(float2*)&C[(size_t)er * ldc + c] =
            make_float2(acc[nt][0] + bv0, acc[nt][1] + bv1);
        *(float2*)&C[(size_t)(er + 8) * ldc + c] =
            make_float2(acc[nt][2] + bv0, acc[nt][3] + bv1);
    }
}

// ---------------- init ----------------
__global__ void init_k(const float* h0l, const float* h0h,
                       const float* bih, const float* bhh)
{
    int i = blockIdx.x * blockDim.x + threadIdx.x;
    if (i < B_ * NHID_) {
        d_hl[0][i] = h0l[i];
        d_hh[0][i] = h0h[i];
    }
    if (i < NG_) d_biasHi[i] = bih[i] + bhh[i];
}

// ---------------- launch ----------------
extern "C" void kernel_launch(void* const* d_in, const int* in_sizes, int n_in,
                              void* d_out, int out_size)
{
    const int*   tokens  = (const int*)d_in[0];
    const int*   measure = (const int*)d_in[1];
    const float* emb     = (const float*)d_in[2];
    const float* Wil     = (const float*)d_in[3];   // [4096][1536]
    const float* Whl     = (const float*)d_in[4];   // [4096][1024]
    const float* bil     = (const float*)d_in[5];
    const float* bhl     = (const float*)d_in[6];
    const float* Wih     = (const float*)d_in[7];   // [4096][1024]
    const float* Whh     = (const float*)d_in[8];   // [4096][1024]
    const float* bih     = (const float*)d_in[9];
    const float* bhh     = (const float*)d_in[10];
    const float* Wd      = (const float*)d_in[11];  // [2048][1024]
    const float* bd      = (const float*)d_in[12];
    const float* h0l     = (const float*)d_in[13];
    const float* c0l     = (const float*)d_in[14];
    const float* h0h     = (const float*)d_in[15];
    const float* c0h     = (const float*)d_in[16];
    float* out = (float*)d_out;

    void* p;
    cudaGetSymbolAddress(&p, d_P);  float* Pp  = (float*)p;
    cudaGetSymbolAddress(&p, d_hs); float* hsP = (float*)p;
    cudaGetSymbolAddress(&p, d_Wp); float* WpP = (float*)p;

    init_k<<<256, 256>>>(h0l, h0h, bih, bhh);

    // frag-pack the recurrent weights (low: Wil cols 512.. + Whl; high: Wih + Whh)
    prepack_k<<<dim3(64, NB_), 512>>>(Wil, NINP_ + NHID_, NINP_, Whl, NHID_, WpP);
    prepack_k<<<dim3(64, NB_), 512>>>(Wih, NHID_, 0, Whh, NHID_,
                                      WpP + (size_t)NB_ * WPC_);

    // P[v][j] = emb[v,:512] @ W_ih_low[j,:512]^T + b_ih_low[j] + b_hh_low[j]
    gemm_k<0><<<dim3(NG_ / 64, NTOK_ / 64), 256>>>(
        emb, NINP_, Wil, NINP_ + NHID_, bil, bhl, Pp, NG_, NINP_);

    // entire 512-step recurrence in one persistent kernel
    hrnn_persist<<<NB_, 256>>>(tokens, measure, c0l, c0h, out, out_size);

    // decode: out[b*T+t][n] = hs[t][b][:] @ W_dec[n][:]^T + b_dec[n]
    gemm_k<1><<<dim3(NTOK_ / 64, (B_ * T_) / 64), 256>>>(
        hsP, 0, Wd, NHID_, bd, (const float*)0, out, NTOK_, NHID_);
}

// round 8
// speedup vs baseline: 1.5347x; 1.2908x over previous
#include <cuda_runtime.h>
#include <math.h>

#define B_    64
#define T_    512
#define NHID_ 1024
#define NG_   4096
#define NTOK_ 2048
#define NINP_ 512
#define NB_   128            // persistent CTAs (one per 8 hidden units)
#define WPC_  65536ULL       // packed-W words per (phase, ub): 64 chunks * 1024

// ---------------- device scratch (static: no allocations) ----------------
__device__ float d_P[(size_t)NTOK_ * NG_];       // 32 MB per-token low-gate base
__device__ float d_hl[2][B_ * NHID_];            // h values stored pre-rounded to tf32
__device__ float d_hh[2][B_ * NHID_];
__device__ float d_hs[(size_t)T_ * B_ * NHID_];  // h_low per step, [t][b][k] (tf32)
__device__ float d_biasHi[NG_];
__device__ float d_Wp[2ULL * NB_ * WPC_];        // 64 MB frag-packed tf32 weights
__device__ unsigned g_cnt;
__device__ unsigned g_gen;

// ---------------- helpers ----------------
__device__ __forceinline__ unsigned tf(float f) {
    unsigned u;
    asm("cvt.rna.tf32.f32 %0, %1;" : "=r"(u) : "f"(f));
    return u;
}
__device__ __forceinline__ float tff(float f) { return __uint_as_float(tf(f)); }

__device__ __forceinline__ void mma_tf32(float* d, const unsigned* a,
                                         unsigned b0, unsigned b1) {
    asm volatile(
        "mma.sync.aligned.m16n8k8.row.col.f32.tf32.tf32.f32 "
        "{%0,%1,%2,%3},{%4,%5,%6,%7},{%8,%9},{%0,%1,%2,%3};\n"
        : "+f"(d[0]), "+f"(d[1]), "+f"(d[2]), "+f"(d[3])
        : "r"(a[0]), "r"(a[1]), "r"(a[2]), "r"(a[3]), "r"(b0), "r"(b1));
}

__device__ __forceinline__ uint4 tf4(float4 v) {
    return make_uint4(tf(v.x), tf(v.y), tf(v.z), tf(v.w));
}

__device__ __forceinline__ float sigm(float x) { return 1.0f / (1.0f + expf(-x)); }

__device__ __forceinline__ unsigned fau(float f) { return __float_as_uint(f); }

__device__ __forceinline__ unsigned s2u(const void* p) {
    return (unsigned)__cvta_generic_to_shared(p);
}

__device__ __forceinline__ void cpa16(unsigned sa, const void* g) {
    asm volatile("cp.async.cg.shared.global [%0], [%1], 16;" :: "r"(sa), "l"(g));
}
__device__ __forceinline__ void cpa_commit() {
    asm volatile("cp.async.commit_group;" ::: "memory");
}
template <int N>
__device__ __forceinline__ void cpa_wait() {
    asm volatile("cp.async.wait_group %0;" :: "n"(N) : "memory");
}

// Grid-wide barrier
__device__ __forceinline__ void gridbar() {
    __threadfence();
    __syncthreads();
    if (threadIdx.x == 0) {
        unsigned gen = *(volatile unsigned*)&g_gen;
        unsigned prev = atomicAdd(&g_cnt, 1u);
        if (prev == NB_ - 1) {
            atomicExch(&g_cnt, 0u);
            __threadfence();
            atomicExch(&g_gen, gen + 1u);
        } else {
            while (*(volatile unsigned*)&g_gen == gen) __nanosleep(32);
        }
    }
    __syncthreads();
}

// ---------------- weight prepack: frag-ready tf32 layout ----------------
// Per (ub, kc): 512 uint2, offset = kw*256 + kk2*128 + nt*32 + lane (== tid),
// holding {W[n][k], W[n][k+4]} where n = nt*8 + (lane>>2)  (gate-col 0..31),
// k = kc*32 + (kw*2+kk2)*8 + (lane&3).
// Gate-col n maps to weight row (n>>3)*NHID + ub*8 + (n&7).
__global__ void __launch_bounds__(512) prepack_k(
    const float* __restrict__ W0, int ldw0, int col0,
    const float* __restrict__ W1, int ldw1,
    float* __restrict__ outp)
{
    const int kc = blockIdx.x, ub = blockIdx.y;
    const int t = threadIdx.x;
    const int lane = t & 31, nt = (t >> 5) & 3, kk2 = (t >> 7) & 1, kw = (t >> 8) & 1;
    const int n = nt * 8 + (lane >> 2);
    const int row = (n >> 3) * NHID_ + ub * 8 + (n & 7);
    const int k = kc * 32 + (kw * 2 + kk2) * 8 + (lane & 3);
    float v0, v1;
    if (kc < 32) {
        v0 = W0[(size_t)row * ldw0 + col0 + k];
        v1 = W0[(size_t)row * ldw0 + col0 + k + 4];
    } else {
        v0 = W1[(size_t)row * ldw1 + (k - 1024)];
        v1 = W1[(size_t)row * ldw1 + (k - 1024) + 4];
    }
    uint2* o = (uint2*)(outp + (size_t)ub * WPC_ + (size_t)kc * 1024);
    o[t] = make_uint2(tf(v0), tf(v1));
}

// ---------------- chunk body (S = stage/slot = kc % 3) ----------------
// A staged via cp.async (3 stages), W via 3-slot register ring (distance 2).
template <int S, int WAITN>
__device__ __forceinline__ void chunk_body(
    int kc,
    float (&As)[3][64][36], uint2 (&w)[3][8], float (&acc)[4][4],
    const float* __restrict__ A0, const float* __restrict__ A1,
    const uint2* __restrict__ wb,
    int r, int c4, int lane, int mw, int kw)
{
    constexpr int SN = (S + 2) % 3;
    // W prefetch: chunk kc+2 -> slot SN (last read in chunk kc-1, done)
    if (kc + 2 < 64) {
        const uint2* wc = wb + (size_t)(kc + 2) * 512;
#pragma unroll
        for (int q = 0; q < 8; q++)
            w[SN][q] = __ldg(wc + (q >> 2) * 128 + (q & 3) * 32);
    }
    // wait for A chunk kc, sync all threads
    cpa_wait<WAITN>();
    __syncthreads();
    // issue A chunk kc+2 -> stage SN (safe: stage SN reads finished pre-sync)
    if (kc + 2 < 64) {
        const int kn = kc + 2;
        const float* src = (kn < 32) ? (A0 + kn * 32) : (A1 + (kn - 32) * 32);
        cpa16(s2u(&As[SN][r][c4]),      src + (size_t)r * NHID_ + c4);
        cpa16(s2u(&As[SN][r + 32][c4]), src + (size_t)(r + 32) * NHID_ + c4);
        cpa_commit();
    }
    // compute chunk kc from stage S
#pragma unroll
    for (int kk2 = 0; kk2 < 2; kk2++) {
        const int ak = (kw * 2 + kk2) * 8 + (lane & 3);
        const int ar = mw * 16 + (lane >> 2);
        unsigned a[4];
        a[0] = fau(As[S][ar][ak]);     a[1] = fau(As[S][ar + 8][ak]);
        a[2] = fau(As[S][ar][ak + 4]); a[3] = fau(As[S][ar + 8][ak + 4]);
#pragma unroll
        for (int nt = 0; nt < 4; nt++)
            mma_tf32(acc[nt], a, w[S][kk2 * 4 + nt].x, w[S][kk2 * 4 + nt].y);
    }
}

// ---------------- gate GEMM for one phase ----------------
// sg2[kw][64][n32] partial gates; caller reads sg2[0]+sg2[1].
__device__ __forceinline__ void gemm_phase(
    float (&As)[3][64][36], float (&sg2)[2][64][34],
    const float* __restrict__ A0, const float* __restrict__ A1,
    const uint2* __restrict__ Wp)
{
    const int tid = threadIdx.x, lane = tid & 31, wid = tid >> 5;
    const int mw = wid >> 1, kw = wid & 1;
    const int r = tid >> 3, c4 = (tid & 7) * 4;

    const uint2* wb = Wp + kw * 256 + lane;

    // prologue: A chunks 0,1 via cp.async; W chunks 0,1 into slots 0,1
    {
        cpa16(s2u(&As[0][r][c4]),      A0 + (size_t)r * NHID_ + c4);
        cpa16(s2u(&As[0][r + 32][c4]), A0 + (size_t)(r + 32) * NHID_ + c4);
        cpa_commit();
        cpa16(s2u(&As[1][r][c4]),      A0 + (size_t)r * NHID_ + 32 + c4);
        cpa16(s2u(&As[1][r + 32][c4]), A0 + (size_t)(r + 32) * NHID_ + 32 + c4);
        cpa_commit();
    }
    uint2 w[3][8];
#pragma unroll
    for (int q = 0; q < 8; q++)
        w[0][q] = __ldg(wb + (q >> 2) * 128 + (q & 3) * 32);
#pragma unroll
    for (int q = 0; q < 8; q++)
        w[1][q] = __ldg(wb + 512 + (q >> 2) * 128 + (q & 3) * 32);

    float acc[4][4] = {};
    for (int kb = 0; kb < 21; kb++) {
        chunk_body<0, 1>(kb * 3,     As, w, acc, A0, A1, wb, r, c4, lane, mw, kw);
        chunk_body<1, 1>(kb * 3 + 1, As, w, acc, A0, A1, wb, r, c4, lane, mw, kw);
        chunk_body<2, 1>(kb * 3 + 2, As, w, acc, A0, A1, wb, r, c4, lane, mw, kw);
    }
    chunk_body<0, 0>(63, As, w, acc, A0, A1, wb, r, c4, lane, mw, kw);

    // dump partial accumulators: sg2[kw][batch][n]
    {
        const int er = mw * 16 + (lane >> 2);
        const int ec = (lane & 3) * 2;
#pragma unroll
        for (int nt = 0; nt < 4; nt++) {
            const int c = nt * 8 + ec;
            *(float2*)&sg2[kw][er][c]     = make_float2(acc[nt][0], acc[nt][1]);
            *(float2*)&sg2[kw][er + 8][c] = make_float2(acc[nt][2], acc[nt][3]);
        }
    }
    __syncthreads();
}

// ---------------- persistent recurrence kernel ----------------
__global__ void __launch_bounds__(256, 1) hrnn_persist(
    const int* __restrict__ tokens, const int* __restrict__ measure,
    const float* __restrict__ c0l, const float* __restrict__ c0h,
    float* __restrict__ out, int out_size)
{
    __shared__ __align__(16) float As[3][64][36];
    __shared__ float sg2[2][64][34];

    const int tid = threadIdx.x;
    const int u0 = blockIdx.x * 8;
    const uint2* WpL = (const uint2*)(d_Wp + (size_t)blockIdx.x * WPC_);
    const uint2* WpH = (const uint2*)(d_Wp + (size_t)(NB_ + blockIdx.x) * WPC_);

    float* hl0 = d_hl[0]; float* hl1 = d_hl[1];
    float* hh0 = d_hh[0]; float* hh1 = d_hh[1];

    const int bA = tid >> 3;
    const int uA = tid & 7;
    const int unit = u0 + uA;
    const int bArr[2] = { bA, bA + 32 };

    float cl[2], ch[2], bv[4];
#pragma unroll
    for (int it = 0; it < 2; it++) {
        cl[it] = c0l[bArr[it] * NHID_ + unit];
        ch[it] = c0h[bArr[it] * NHID_ + unit];
    }
#pragma unroll
    for (int g = 0; g < 4; g++) bv[g] = __ldg(&d_biasHi[g * NHID_ + unit]);
    const int mval = *measure;

    for (int t = 0; t < T_; t++) {
        float* hlA = (t & 1) ? hl1 : hl0;
        float* hlN = (t & 1) ? hl0 : hl1;
        float* hhA = (t & 1) ? hh1 : hh0;
        float* hhN = (t & 1) ? hh0 : hh1;

        // prefetch epilogue operands for the low phase
        int tok[2];
        float pv[2][4];
#pragma unroll
        for (int it = 0; it < 2; it++) {
            tok[it] = __ldg(&tokens[bArr[it] * T_ + t]);
            const float* bp = d_P + (size_t)tok[it] * NG_ + unit;
#pragma unroll
            for (int g = 0; g < 4; g++) pv[it][g] = __ldg(bp + g * NHID_);
        }

        // ---- low cell: inp = [emb(tok) | h_h]; emb folded into d_P ----
        gemm_phase(As, sg2, hhA, hlA, WpL);
#pragma unroll
        for (int it = 0; it < 2; it++) {
            int b = bArr[it];
            float gi = sg2[0][b][uA]      + sg2[1][b][uA]      + pv[it][0];
            float gf = sg2[0][b][8 + uA]  + sg2[1][b][8 + uA]  + pv[it][1];
            float gg = sg2[0][b][16 + uA] + sg2[1][b][16 + uA] + pv[it][2];
            float go = sg2[0][b][24 + uA] + sg2[1][b][24 + uA] + pv[it][3];
            float cn = sigm(gf) * cl[it] + sigm(gi) * tanhf(gg);
            float hn = tff(sigm(go) * tanhf(cn));   // pre-rounded to tf32
            cl[it] = cn;
            hlN[b * NHID_ + unit] = hn;
            d_hs[((size_t)t * B_ + b) * NHID_ + unit] = hn;
        }
        gridbar();

        // prefetch kept-path previous high h
        float hp[2];
#pragma unroll
        for (int it = 0; it < 2; it++)
            hp[it] = __ldcg(&hhA[bArr[it] * NHID_ + unit]);

        // ---- high cell: masked update ----
        gemm_phase(As, sg2, hlN, hhA, WpH);
#pragma unroll
        for (int it = 0; it < 2; it++) {
            int b = bArr[it];
            float gi = sg2[0][b][uA]      + sg2[1][b][uA]      + bv[0];
            float gf = sg2[0][b][8 + uA]  + sg2[1][b][8 + uA]  + bv[1];
            float gg = sg2[0][b][16 + uA] + sg2[1][b][16 + uA] + bv[2];
            float go = sg2[0][b][24 + uA] + sg2[1][b][24 + uA] + bv[3];
            float cn = sigm(gf) * ch[it] + sigm(gi) * tanhf(gg);
            float hn = tff(sigm(go) * tanhf(cn));
            bool m = (tok[it] == mval);
            ch[it] = m ? cn : ch[it];
            hhN[b * NHID_ + unit] = m ? hn : hp[it];
        }
        gridbar();
    }

    // final states (t=511 wrote ping 0); c still exact in registers
    size_t q = (size_t)B_ * T_ * NTOK_;
    size_t S = (size_t)B_ * NHID_;
    if ((size_t)out_size >= q + 4 * S) {
#pragma unroll
        for (int it = 0; it < 2; it++) {
            size_t o = (size_t)bArr[it] * NHID_ + unit;
            out[q + o]         = __ldcg(&hl0[o]);
            out[q + S + o]     = cl[it];
            out[q + 2 * S + o] = __ldcg(&hh0[o]);
            out[q + 3 * S + o] = ch[it];
        }
    }
}

// ---------------- generic tf32 GEMM: C[MxN] = A[MxK] @ Bw[N,K]^T + bias ----
template <int REMAP>
__global__ void __launch_bounds__(256) gemm_k(
    const float* __restrict__ A, int lda,
    const float* __restrict__ Bw, int ldb,
    const float* __restrict__ bias1, const float* __restrict__ bias2,
    float* __restrict__ C, int ldc, int K)
{
    __shared__ unsigned As[64][36];
    __shared__ unsigned Bs[64][36];

    const int tid = threadIdx.x, lane = tid & 31, wid = tid >> 5;
    const int m0 = blockIdx.y * 64, n0 = blockIdx.x * 64;

    const float* Ab;
    long as;
    if (REMAP) {
        Ab = A + ((size_t)(m0 % T_) * B_ + (m0 / T_)) * NHID_;
        as = (long)B_ * NHID_;
    } else {
        Ab = A + (size_t)m0 * lda;
        as = lda;
    }

    const int r = tid >> 3, c4 = (tid & 7) * 4;
    float4 pa0 = *(const float4*)(Ab + (long)r * as + c4);
    float4 pa1 = *(const float4*)(Ab + (long)(r + 32) * as + c4);
    float4 pb0 = *(const float4*)(Bw + (size_t)(n0 + r) * ldb + c4);
    float4 pb1 = *(const float4*)(Bw + (size_t)(n0 + r + 32) * ldb + c4);

    const int mw = wid >> 1, nw = wid & 1;
    float acc[4][4] = {};

    const int nch = K / 32;
    for (int kc = 0; kc < nch; kc++) {
        *(uint4*)&As[r][c4]      = tf4(pa0);
        *(uint4*)&As[r + 32][c4] = tf4(pa1);
        *(uint4*)&Bs[r][c4]      = tf4(pb0);
        *(uint4*)&Bs[r + 32][c4] = tf4(pb1);
        __syncthreads();
        if (kc + 1 < nch) {
            int ko = (kc + 1) * 32 + c4;
            pa0 = *(const float4*)(Ab + (long)r * as + ko);
            pa1 = *(const float4*)(Ab + (long)(r + 32) * as + ko);
            pb0 = *(const float4*)(Bw + (size_t)(n0 + r) * ldb + ko);
            pb1 = *(const float4*)(Bw + (size_t)(n0 + r + 32) * ldb + ko);
        }
#pragma unroll
        for (int kk = 0; kk < 4; kk++) {
            const int ak = kk * 8 + (lane & 3);
            const int ar = mw * 16 + (lane >> 2);
            unsigned a[4];
            a[0] = As[ar][ak];     a[1] = As[ar + 8][ak];
            a[2] = As[ar][ak + 4]; a[3] = As[ar + 8][ak + 4];
#pragma unroll
            for (int nt = 0; nt < 4; nt++) {
                const int br = nw * 32 + nt * 8 + (lane >> 2);
                mma_tf32(acc[nt], a, Bs[br][ak], Bs[br][ak + 4]);
            }
        }
        __syncthreads();
    }

    const int er = m0 + mw * 16 + (lane >> 2);
    const int ec0 = n0 + nw * 32 + (lane & 3) * 2;
#pragma unroll
    for (int nt = 0; nt < 4; nt++) {
        int c = ec0 + nt * 8;
        float bv0 = bias1[c]     + (bias2 ? bias2[c]     : 0.0f);
        float bv1 = bias1[c + 1] + (bias2 ? bias2[c + 1] : 0.0f);
        *(float2*)&C[(size_t)er * ldc + c] =
            make_float2(acc[nt][0] + bv0, acc[nt][1] + bv1);
        *(float2*)&C[(size_t)(er + 8) * ldc + c] =
            make_float2(acc[nt][2] + bv0, acc[nt][3] + bv1);
    }
}

// ---------------- init ----------------
__global__ void init_k(const float* h0l, const float* h0h,
                       const float* bih, const float* bhh)
{
    int i = blockIdx.x * blockDim.x + threadIdx.x;
    if (i < B_ * NHID_) {
        d_hl[0][i] = __uint_as_float(tf(h0l[i]));   // pre-round h to tf32
        d_hh[0][i] = __uint_as_float(tf(h0h[i]));
    }
    if (i < NG_) d_biasHi[i] = bih[i] + bhh[i];
}

// ---------------- launch ----------------
extern "C" void kernel_launch(void* const* d_in, const int* in_sizes, int n_in,
                              void* d_out, int out_size)
{
    const int*   tokens  = (const int*)d_in[0];
    const int*   measure = (const int*)d_in[1];
    const float* emb     = (const float*)d_in[2];
    const float* Wil     = (const float*)d_in[3];   // [4096][1536]
    const float* Whl     = (const float*)d_in[4];   // [4096][1024]
    const float* bil     = (const float*)d_in[5];
    const float* bhl     = (const float*)d_in[6];
    const float* Wih     = (const float*)d_in[7];   // [4096][1024]
    const float* Whh     = (const float*)d_in[8];   // [4096][1024]
    const float* bih     = (const float*)d_in[9];
    const float* bhh     = (const float*)d_in[10];
    const float* Wd      = (const float*)d_in[11];  // [2048][1024]
    const float* bd      = (const float*)d_in[12];
    const float* h0l     = (const float*)d_in[13];
    const float* c0l     = (const float*)d_in[14];
    const float* h0h     = (const float*)d_in[15];
    const float* c0h     = (const float*)d_in[16];
    float* out = (float*)d_out;

    void* p;
    cudaGetSymbolAddress(&p, d_P);  float* Pp  = (float*)p;
    cudaGetSymbolAddress(&p, d_hs); float* hsP = (float*)p;
    cudaGetSymbolAddress(&p, d_Wp); float* WpP = (float*)p;

    init_k<<<256, 256>>>(h0l, h0h, bih, bhh);

    // frag-pack recurrent weights (low: Wil cols 512.. + Whl; high: Wih + Whh)
    prepack_k<<<dim3(64, NB_), 512>>>(Wil, NINP_ + NHID_, NINP_, Whl, NHID_, WpP);
    prepack_k<<<dim3(64, NB_), 512>>>(Wih, NHID_, 0, Whh, NHID_,
                                      WpP + (size_t)NB_ * WPC_);

    // P[v][j] = emb[v,:512] @ W_ih_low[j,:512]^T + b_ih_low[j] + b_hh_low[j]
    gemm_k<0><<<dim3(NG_ / 64, NTOK_ / 64), 256>>>(
        emb, NINP_, Wil, NINP_ + NHID_, bil, bhl, Pp, NG_, NINP_);

    // entire 512-step recurrence in one persistent kernel
    hrnn_persist<<<NB_, 256>>>(tokens, measure, c0l, c0h, out, out_size);

    // decode: out[b*T+t][n] = hs[t][b][:] @ W_dec[n][:]^T + b_dec[n]
    gemm_k<1><<<dim3(NTOK_ / 64, (B_ * T_) / 64), 256>>>(
        hsP, 0, Wd, NHID_, bd, (const float*)0, out, NTOK_, NHID_);
}